// round 1
// baseline (speedup 1.0000x reference)
#include <cuda_runtime.h>
#include <math.h>

// Problem dims
#define Bq 32
#define Tq 96
#define Hq 512
#define Eq 512
#define Vq 10000
#define Fq 2048
#define NJ 2560          // fused output cols: ingate 0:512 | outgate 512:1024 | cell 1024:1536 | f1 1536:2048 | f2 2048:2560
#define KK 1024          // fused input K: [xa|xf] for pre, [ha_h|hf_h] for rec
#define MR (Bq*Tq)       // 3072 rows
#define MAXROWS 608      // max rows in one stage (19 nodes * 32)

// -------- device scratch (static: no allocations allowed) --------
__device__ float g_Wpre[NJ*KK];    // [j][k] K-major
__device__ float g_Wrec[NJ*KK];    // [j][k] K-major
__device__ float g_bias[NJ];
__device__ float g_att [Bq*Eq];
__device__ float g_attI[Bq*Hq];
__device__ float g_Xpre[MR*KK];
__device__ float g_pre [MR*NJ];
__device__ float g_Xrec[MAXROWS*KK];
__device__ float g_Rp  [4*MAXROWS*NJ];  // split-K partials
__device__ float g_h   [Bq*Tq*Hq];
__device__ float g_c   [Bq*Tq*Hq];

// 13 wavefront stages: (depth, sibling-position) groups of the ternary tree
__constant__ int c_nodes[96] = {
    0,
    1, 2, 3,
    4,7,10,  5,8,11,  6,9,12,
    13,16,19,22,25,28,31,34,37,
    14,17,20,23,26,29,32,35,38,
    15,18,21,24,27,30,33,36,39,
    40,43,46,49,52,55,58,61,64,67,70,73,76,79,82,85,88,91,94,
    41,44,47,50,53,56,59,62,65,68,71,74,77,80,83,86,89,92,95,
    42,45,48,51,54,57,60,63,66,69,72,75,78,81,84,87,90,93
};

__device__ __forceinline__ float sigf(float x) { return 1.0f / (1.0f + expf(-x)); }

// ---------------- setup: rearrange weights into fused K-major blocks ----------------
__global__ __launch_bounds__(256) void k_setup(
    const float* __restrict__ W_H,  const float* __restrict__ W_I,
    const float* __restrict__ W_f1, const float* __restrict__ W_f2,
    const float* __restrict__ b_H,  const float* __restrict__ b_I,
    const float* __restrict__ b_f1, const float* __restrict__ b_f2)
{
    int j = blockIdx.x;             // 0..2559
    int tid = threadIdx.x;
    for (int k = tid; k < KK; k += 256) {
        float wp, wr;
        if (j < 1024) {                       // gates: W_H [1024, 2048] cols xa|xf|ha|hf
            wp = W_H[j*2048 + k];
            wr = W_H[j*2048 + 1024 + k];
        } else if (j < 1536) {                // cell: W_I [512, 2560] cols xa|xf|ha|hf|att
            int jj = j - 1024;
            wp = W_I[jj*2560 + k];
            wr = W_I[jj*2560 + 1024 + k];
        } else if (j < 2048) {                // f1: W_f1 [512, 1024] cols xa|ha  (only xa/ha halves)
            int jj = j - 1536;
            wp = (k < 512) ? W_f1[jj*1024 + k]       : 0.0f;
            wr = (k < 512) ? W_f1[jj*1024 + 512 + k] : 0.0f;
        } else {                              // f2: W_f2 [512, 1024] cols xf|hf
            int jj = j - 2048;
            wp = (k >= 512) ? W_f2[jj*1024 + (k - 512)] : 0.0f;
            wr = (k >= 512) ? W_f2[jj*1024 + k]         : 0.0f;
        }
        g_Wpre[j*KK + k] = wp;
        g_Wrec[j*KK + k] = wr;
    }
    if (tid == 0) {
        g_bias[j] = (j < 1024) ? b_H[j] :
                    (j < 1536) ? b_I[j-1024] :
                    (j < 2048) ? b_f1[j-1536] : b_f2[j-2048];
    }
}

// ---------------- att = fc_feats @ fc_W.T + fc_b  (one warp per output) ----------------
__global__ __launch_bounds__(256) void k_att(
    const float* __restrict__ fc_feats, const float* __restrict__ fc_W,
    const float* __restrict__ fc_b)
{
    int e = blockIdx.x * 8 + (threadIdx.x >> 5);
    int b = blockIdx.y;
    int lane = threadIdx.x & 31;
    float s = 0.0f;
    for (int f = lane; f < Fq; f += 32)
        s += fc_feats[b*Fq + f] * fc_W[e*Fq + f];
    #pragma unroll
    for (int o = 16; o > 0; o >>= 1) s += __shfl_down_sync(0xffffffffu, s, o);
    if (lane == 0) g_att[b*Eq + e] = s + fc_b[e];
}

// ---------------- attI = att @ W_I[:, 2048:2560].T ----------------
__global__ __launch_bounds__(256) void k_attI(const float* __restrict__ W_I)
{
    int j = blockIdx.x * 8 + (threadIdx.x >> 5);
    int b = blockIdx.y;
    int lane = threadIdx.x & 31;
    float s = 0.0f;
    for (int k = lane; k < 512; k += 32)
        s += g_att[b*Eq + k] * W_I[j*2560 + 2048 + k];
    #pragma unroll
    for (int o = 16; o > 0; o >>= 1) s += __shfl_down_sync(0xffffffffu, s, o);
    if (lane == 0) g_attI[b*Hq + j] = s;
}

// ---------------- Xpre[r][k] = [xa | xf] embedding gather ----------------
__global__ __launch_bounds__(256) void k_xpre(
    const int* __restrict__ word, const int* __restrict__ father,
    const float* __restrict__ embed)
{
    int r = blockIdx.x;       // r = b*96 + t
    int b = r / Tq, t = r % Tq;
    int f  = father[b*Tq + t];
    int wa = word[b*Tq + f];
    int wf = (t > 0) ? word[b*Tq + t - 1] : 0;
    bool pa = (t > 0);
    bool sb = (t > 0) && (((t - 1) % 3) != 0);
    for (int k = threadIdx.x; k < KK; k += 256) {
        float v;
        if (k < 512) v = pa ? embed[wa*Eq + k]        : 0.0f;
        else         v = sb ? embed[wf*Eq + (k-512)]  : 0.0f;
        g_Xpre[r*KK + k] = v;
    }
}

// ---------------- GEMM: pre = Xpre[3072,1024] @ Wpre^T + bias + attI(cell cols) ----------------
__global__ __launch_bounds__(256) void k_gemm_pre()
{
    __shared__ float As[16][68];
    __shared__ float Bs[16][68];
    int tid = threadIdx.x;
    int n0 = blockIdx.x * 64, m0 = blockIdx.y * 64;
    int ttx = tid & 15, tty = tid >> 4;
    int ar = tid >> 2, ac = (tid & 3) << 2;
    float acc[4][4];
    #pragma unroll
    for (int i = 0; i < 4; i++)
        #pragma unroll
        for (int j = 0; j < 4; j++) acc[i][j] = 0.0f;

    for (int k0 = 0; k0 < KK; k0 += 16) {
        float4 av = *(const float4*)(g_Xpre + (m0 + ar)*KK + k0 + ac);
        As[ac+0][ar] = av.x; As[ac+1][ar] = av.y; As[ac+2][ar] = av.z; As[ac+3][ar] = av.w;
        float4 bv = *(const float4*)(g_Wpre + (n0 + ar)*KK + k0 + ac);
        Bs[ac+0][ar] = bv.x; Bs[ac+1][ar] = bv.y; Bs[ac+2][ar] = bv.z; Bs[ac+3][ar] = bv.w;
        __syncthreads();
        #pragma unroll
        for (int kk = 0; kk < 16; kk++) {
            float a[4], bb[4];
            #pragma unroll
            for (int i = 0; i < 4; i++) a[i]  = As[kk][(tty<<2) + i];
            #pragma unroll
            for (int j = 0; j < 4; j++) bb[j] = Bs[kk][(ttx<<2) + j];
            #pragma unroll
            for (int i = 0; i < 4; i++)
                #pragma unroll
                for (int j = 0; j < 4; j++) acc[i][j] += a[i] * bb[j];
        }
        __syncthreads();
    }
    #pragma unroll
    for (int i = 0; i < 4; i++) {
        int m = m0 + (tty<<2) + i;
        int bb2 = m / Tq;
        #pragma unroll
        for (int j = 0; j < 4; j++) {
            int n = n0 + (ttx<<2) + j;
            float v = acc[i][j] + g_bias[n];
            if (n >= 1024 && n < 1536) v += g_attI[bb2*Hq + (n - 1024)];
            g_pre[m*NJ + n] = v;
        }
    }
}

// ---------------- per-stage: gather Xrec = [ha_h | hf_h] ----------------
__global__ __launch_bounds__(256) void k_gather(int base, const int* __restrict__ father)
{
    int row = blockIdx.x;
    int nn = row >> 5, b = row & 31;
    int i = c_nodes[base + nn];
    int f = father[b*Tq + i];
    bool pa = (i > 0);
    bool sb = (i > 0) && (((i - 1) % 3) != 0);
    for (int k = threadIdx.x; k < KK; k += 256) {
        float v;
        if (k < 512) v = pa ? g_h[(b*Tq + f)*Hq + k]           : 0.0f;
        else         v = sb ? g_h[(b*Tq + i - 1)*Hq + (k-512)] : 0.0f;
        g_Xrec[row*KK + k] = v;
    }
}

// ---------------- per-stage rec GEMM: Rp[z] = Xrec[rows,256@z] @ Wrec^T  (split-K=4) ----------------
__global__ __launch_bounds__(256) void k_gemm_rec()
{
    __shared__ float As[16][36];
    __shared__ float Bs[16][68];
    int tid = threadIdx.x;
    int n0 = blockIdx.x * 64, m0 = blockIdx.y * 32, z = blockIdx.z;
    int ttx = tid & 15, tty = tid >> 4;    // tty 0..15 -> 2 rows each
    int ac = (tid & 3) << 2;
    float acc[2][4];
    #pragma unroll
    for (int i = 0; i < 2; i++)
        #pragma unroll
        for (int j = 0; j < 4; j++) acc[i][j] = 0.0f;

    int kend = z*256 + 256;
    for (int k0 = z*256; k0 < kend; k0 += 16) {
        if (tid < 128) {
            int arA = tid >> 2;   // 0..31
            float4 av = *(const float4*)(g_Xrec + (m0 + arA)*KK + k0 + ac);
            As[ac+0][arA] = av.x; As[ac+1][arA] = av.y; As[ac+2][arA] = av.z; As[ac+3][arA] = av.w;
        }
        int arB = tid >> 2;       // 0..63
        float4 bv = *(const float4*)(g_Wrec + (n0 + arB)*KK + k0 + ac);
        Bs[ac+0][arB] = bv.x; Bs[ac+1][arB] = bv.y; Bs[ac+2][arB] = bv.z; Bs[ac+3][arB] = bv.w;
        __syncthreads();
        #pragma unroll
        for (int kk = 0; kk < 16; kk++) {
            float a[2], bb[4];
            #pragma unroll
            for (int i = 0; i < 2; i++) a[i]  = As[kk][(tty<<1) + i];
            #pragma unroll
            for (int j = 0; j < 4; j++) bb[j] = Bs[kk][(ttx<<2) + j];
            #pragma unroll
            for (int i = 0; i < 2; i++)
                #pragma unroll
                for (int j = 0; j < 4; j++) acc[i][j] += a[i] * bb[j];
        }
        __syncthreads();
    }
    #pragma unroll
    for (int i = 0; i < 2; i++) {
        int row = m0 + (tty<<1) + i;
        #pragma unroll
        for (int j = 0; j < 4; j++) {
            int n = n0 + (ttx<<2) + j;
            g_Rp[(z*MAXROWS + row)*NJ + n] = acc[i][j];
        }
    }
}

// ---------------- per-stage epilogue: combine partials, nonlinearities, update h/c ----------------
__global__ __launch_bounds__(256) void k_epi(int base, const int* __restrict__ father)
{
    int row = blockIdx.x;
    int u = blockIdx.y * 256 + threadIdx.x;   // 0..511
    int nn = row >> 5, b = row & 31;
    int i = c_nodes[base + nn];
    int f = father[b*Tq + i];
    int pr = (b*Tq + i)*NJ;
    float Rv[5];
    #pragma unroll
    for (int q = 0; q < 5; q++) {
        int j = q*512 + u;
        float v = g_pre[pr + j];
        v += g_Rp[(0*MAXROWS + row)*NJ + j];
        v += g_Rp[(1*MAXROWS + row)*NJ + j];
        v += g_Rp[(2*MAXROWS + row)*NJ + j];
        v += g_Rp[(3*MAXROWS + row)*NJ + j];
        Rv[q] = v;
    }
    float ig = sigf(Rv[0]);
    float og = sigf(Rv[1]);
    float cg = tanhf(Rv[2]);
    float f1 = sigf(Rv[3]);
    float f2 = sigf(Rv[4]);
    bool pa = (i > 0);
    bool sb = (i > 0) && (((i - 1) % 3) != 0);
    float hac = pa ? g_c[(b*Tq + f)*Hq + u]     : 0.0f;
    float hfc = sb ? g_c[(b*Tq + i - 1)*Hq + u] : 0.0f;
    float c = f1*hac + f2*hfc + ig*cg;
    float h = og * tanhf(c);
    g_h[(b*Tq + i)*Hq + u] = h;
    g_c[(b*Tq + i)*Hq + u] = c;
}

// ---------------- logits GEMM: out = h[3072,512] @ logit_W[10000,512]^T + logit_b ----------------
__global__ __launch_bounds__(256) void k_gemm_logits(
    const float* __restrict__ logit_W, const float* __restrict__ logit_b,
    float* __restrict__ out)
{
    __shared__ float As[16][68];
    __shared__ float Bs[16][68];
    int tid = threadIdx.x;
    int n0 = blockIdx.x * 64, m0 = blockIdx.y * 64;
    int ttx = tid & 15, tty = tid >> 4;
    int ar = tid >> 2, ac = (tid & 3) << 2;
    float acc[4][4];
    #pragma unroll
    for (int i = 0; i < 4; i++)
        #pragma unroll
        for (int j = 0; j < 4; j++) acc[i][j] = 0.0f;

    int bn = n0 + ar;
    for (int k0 = 0; k0 < Hq; k0 += 16) {
        float4 av = *(const float4*)(g_h + (m0 + ar)*Hq + k0 + ac);
        As[ac+0][ar] = av.x; As[ac+1][ar] = av.y; As[ac+2][ar] = av.z; As[ac+3][ar] = av.w;
        float4 bv = make_float4(0.f, 0.f, 0.f, 0.f);
        if (bn < Vq) bv = *(const float4*)(logit_W + bn*Hq + k0 + ac);
        Bs[ac+0][ar] = bv.x; Bs[ac+1][ar] = bv.y; Bs[ac+2][ar] = bv.z; Bs[ac+3][ar] = bv.w;
        __syncthreads();
        #pragma unroll
        for (int kk = 0; kk < 16; kk++) {
            float a[4], bb[4];
            #pragma unroll
            for (int i = 0; i < 4; i++) a[i]  = As[kk][(tty<<2) + i];
            #pragma unroll
            for (int j = 0; j < 4; j++) bb[j] = Bs[kk][(ttx<<2) + j];
            #pragma unroll
            for (int i = 0; i < 4; i++)
                #pragma unroll
                for (int j = 0; j < 4; j++) acc[i][j] += a[i] * bb[j];
        }
        __syncthreads();
    }
    #pragma unroll
    for (int i = 0; i < 4; i++) {
        int m = m0 + (tty<<2) + i;
        #pragma unroll
        for (int j = 0; j < 4; j++) {
            int n = n0 + (ttx<<2) + j;
            if (n < Vq) out[m*Vq + n] = acc[i][j] + logit_b[n];
        }
    }
}

// ---------------- in-place log_softmax over V ----------------
__global__ __launch_bounds__(256) void k_softmax(float* __restrict__ out)
{
    extern __shared__ float sx[];       // 10000 floats
    __shared__ float red[256];
    int r = blockIdx.x;
    int tid = threadIdx.x;
    float* px = out + (long)r * Vq;
    float m = -1e30f;
    for (int v = tid; v < Vq; v += 256) {
        float x = px[v];
        sx[v] = x;
        m = fmaxf(m, x);
    }
    red[tid] = m; __syncthreads();
    for (int s = 128; s > 0; s >>= 1) {
        if (tid < s) red[tid] = fmaxf(red[tid], red[tid + s]);
        __syncthreads();
    }
    float mx = red[0];
    __syncthreads();
    float s = 0.0f;
    for (int v = tid; v < Vq; v += 256) s += expf(sx[v] - mx);
    red[tid] = s; __syncthreads();
    for (int st = 128; st > 0; st >>= 1) {
        if (tid < st) red[tid] += red[tid + st];
        __syncthreads();
    }
    float ls = logf(red[0]);
    for (int v = tid; v < Vq; v += 256) px[v] = sx[v] - mx - ls;
}

// ---------------- launch ----------------
extern "C" void kernel_launch(void* const* d_in, const int* in_sizes, int n_in,
                              void* d_out, int out_size)
{
    const int*   word     = (const int*)  d_in[0];
    const int*   father   = (const int*)  d_in[1];
    const float* fc_feats = (const float*)d_in[2];
    const float* embed    = (const float*)d_in[3];
    const float* fc_W     = (const float*)d_in[4];
    const float* fc_b     = (const float*)d_in[5];
    const float* W_f1     = (const float*)d_in[6];
    const float* b_f1     = (const float*)d_in[7];
    const float* W_f2     = (const float*)d_in[8];
    const float* b_f2     = (const float*)d_in[9];
    const float* W_H      = (const float*)d_in[10];
    const float* b_H      = (const float*)d_in[11];
    const float* W_I      = (const float*)d_in[12];
    const float* b_I      = (const float*)d_in[13];
    const float* logit_W  = (const float*)d_in[14];
    const float* logit_b  = (const float*)d_in[15];
    float* out = (float*)d_out;

    k_setup<<<NJ, 256>>>(W_H, W_I, W_f1, W_f2, b_H, b_I, b_f1, b_f2);
    k_att <<<dim3(Eq/8, Bq), 256>>>(fc_feats, fc_W, fc_b);
    k_attI<<<dim3(Hq/8, Bq), 256>>>(W_I);
    k_xpre<<<MR, 256>>>(word, father, embed);
    k_gemm_pre<<<dim3(NJ/64, MR/64), 256>>>();

    static const int sbase[13] = {0,1,2,3,4,7,10,13,22,31,40,59,78};
    static const int scnt [13] = {1,1,1,1,3,3,3,9,9,9,19,19,18};
    for (int s = 0; s < 13; s++) {
        int n = scnt[s];
        int rows = n * 32;
        k_gather<<<rows, 256>>>(sbase[s], father);
        k_gemm_rec<<<dim3(NJ/64, n, 4), 256>>>();
        k_epi<<<dim3(rows, 2), 256>>>(sbase[s], father);
    }

    k_gemm_logits<<<dim3((Vq + 63)/64, MR/64), 256>>>(logit_W, logit_b, out);
    k_softmax<<<MR, 256, Vq * sizeof(float)>>>(out);
}

// round 2
// speedup vs baseline: 2.1904x; 2.1904x over previous
#include <cuda_runtime.h>
#include <math.h>

// Problem dims
#define Bq 32
#define Tq 96
#define Hq 512
#define Eq 512
#define Vq 10000
#define Fq 2048
#define NJ 2560          // fused cols: ingate 0:512 | outgate 512:1024 | cell 1024:1536 | f1 1536:2048 | f2 2048:2560
#define KK 1024          // fused K: [xa|xf] (pre) / [ha_h|hf_h] (rec)
#define MR (Bq*Tq)       // 3072
#define MAXROWS 608

// -------- device scratch --------
__device__ float g_Wpre[NJ*KK];
__device__ float g_Wrec[NJ*KK];
__device__ float g_bias[NJ];
__device__ float g_att [Bq*Eq];
__device__ float g_attI[Bq*Hq];
__device__ float g_Xpre[MR*KK];
__device__ float g_pre [MR*NJ];
__device__ float g_Rp  [4*MAXROWS*NJ];
__device__ float g_h   [Bq*Tq*Hq];
__device__ float g_c   [Bq*Tq*Hq];

__constant__ int c_nodes[96] = {
    0,
    1, 2, 3,
    4,7,10,  5,8,11,  6,9,12,
    13,16,19,22,25,28,31,34,37,
    14,17,20,23,26,29,32,35,38,
    15,18,21,24,27,30,33,36,39,
    40,43,46,49,52,55,58,61,64,67,70,73,76,79,82,85,88,91,94,
    41,44,47,50,53,56,59,62,65,68,71,74,77,80,83,86,89,92,95,
    42,45,48,51,54,57,60,63,66,69,72,75,78,81,84,87,90,93
};

__device__ __forceinline__ float sigf(float x) { return 1.0f / (1.0f + expf(-x)); }

__device__ __forceinline__ unsigned f2tf(float x) {
    unsigned r; asm("cvt.rna.tf32.f32 %0, %1;\n" : "=r"(r) : "f"(x)); return r;
}
__device__ __forceinline__ void mma_tf32(float* d, const unsigned* a, const unsigned* b) {
    asm volatile("mma.sync.aligned.m16n8k8.row.col.f32.tf32.tf32.f32 "
        "{%0,%1,%2,%3}, {%4,%5,%6,%7}, {%8,%9}, {%0,%1,%2,%3};\n"
        : "+f"(d[0]), "+f"(d[1]), "+f"(d[2]), "+f"(d[3])
        : "r"(a[0]), "r"(a[1]), "r"(a[2]), "r"(a[3]), "r"(b[0]), "r"(b[1]));
}

// ---------------- setup ----------------
__global__ __launch_bounds__(256) void k_setup(
    const float* __restrict__ W_H,  const float* __restrict__ W_I,
    const float* __restrict__ W_f1, const float* __restrict__ W_f2,
    const float* __restrict__ b_H,  const float* __restrict__ b_I,
    const float* __restrict__ b_f1, const float* __restrict__ b_f2)
{
    int j = blockIdx.x;
    int tid = threadIdx.x;
    for (int k = tid; k < KK; k += 256) {
        float wp, wr;
        if (j < 1024) {
            wp = W_H[j*2048 + k];
            wr = W_H[j*2048 + 1024 + k];
        } else if (j < 1536) {
            int jj = j - 1024;
            wp = W_I[jj*2560 + k];
            wr = W_I[jj*2560 + 1024 + k];
        } else if (j < 2048) {
            int jj = j - 1536;
            wp = (k < 512) ? W_f1[jj*1024 + k]       : 0.0f;
            wr = (k < 512) ? W_f1[jj*1024 + 512 + k] : 0.0f;
        } else {
            int jj = j - 2048;
            wp = (k >= 512) ? W_f2[jj*1024 + (k - 512)] : 0.0f;
            wr = (k >= 512) ? W_f2[jj*1024 + k]         : 0.0f;
        }
        g_Wpre[j*KK + k] = wp;
        g_Wrec[j*KK + k] = wr;
    }
    if (tid == 0) {
        g_bias[j] = (j < 1024) ? b_H[j] :
                    (j < 1536) ? b_I[j-1024] :
                    (j < 2048) ? b_f1[j-1536] : b_f2[j-2048];
    }
}

// ---------------- att / attI ----------------
__global__ __launch_bounds__(256) void k_att(
    const float* __restrict__ fc_feats, const float* __restrict__ fc_W,
    const float* __restrict__ fc_b)
{
    int e = blockIdx.x * 8 + (threadIdx.x >> 5);
    int b = blockIdx.y;
    int lane = threadIdx.x & 31;
    float s = 0.0f;
    for (int f = lane; f < Fq; f += 32)
        s += fc_feats[b*Fq + f] * fc_W[e*Fq + f];
    #pragma unroll
    for (int o = 16; o > 0; o >>= 1) s += __shfl_down_sync(0xffffffffu, s, o);
    if (lane == 0) g_att[b*Eq + e] = s + fc_b[e];
}

__global__ __launch_bounds__(256) void k_attI(const float* __restrict__ W_I)
{
    int j = blockIdx.x * 8 + (threadIdx.x >> 5);
    int b = blockIdx.y;
    int lane = threadIdx.x & 31;
    float s = 0.0f;
    for (int k = lane; k < 512; k += 32)
        s += g_att[b*Eq + k] * W_I[j*2560 + 2048 + k];
    #pragma unroll
    for (int o = 16; o > 0; o >>= 1) s += __shfl_down_sync(0xffffffffu, s, o);
    if (lane == 0) g_attI[b*Hq + j] = s;
}

// ---------------- Xpre gather ----------------
__global__ __launch_bounds__(256) void k_xpre(
    const int* __restrict__ word, const int* __restrict__ father,
    const float* __restrict__ embed)
{
    int r = blockIdx.x;
    int b = r / Tq, t = r % Tq;
    int f  = father[b*Tq + t];
    int wa = word[b*Tq + f];
    int wf = (t > 0) ? word[b*Tq + t - 1] : 0;
    bool pa = (t > 0);
    bool sb = (t > 0) && (((t - 1) % 3) != 0);
    for (int k = threadIdx.x; k < KK; k += 256) {
        float v;
        if (k < 512) v = pa ? embed[wa*Eq + k]        : 0.0f;
        else         v = sb ? embed[wf*Eq + (k-512)]  : 0.0f;
        g_Xpre[r*KK + k] = v;
    }
}

// ---------------- tf32 GEMM: pre = Xpre[3072,1024] @ Wpre^T + bias (+attI) ----------------
// BM=64 BN=128 BK=16, 256 thr, warp grid 2(m)x4(n), warp tile 32x32
__global__ __launch_bounds__(256, 2) void k_gemm_pre_tc()
{
    __shared__ unsigned As[64][20];
    __shared__ unsigned Bs[128][20];
    const int tid = threadIdx.x;
    const int wid = tid >> 5, lane = tid & 31;
    const int g = lane >> 2, tg = lane & 3;
    const int warpM = wid & 1, warpN = wid >> 1;
    const int m0 = blockIdx.y * 64, n0 = blockIdx.x * 128;
    const int rowA = tid >> 2, cA = (tid & 3) << 2;
    const int rowB = tid >> 2, cB = cA;
    const float* Ag = g_Xpre + (m0 + rowA)*KK + cA;
    const float* Bg = g_Wpre + (n0 + rowB)*KK + cB;

    float acc[2][4][4];
    #pragma unroll
    for (int i = 0; i < 2; i++)
        #pragma unroll
        for (int j = 0; j < 4; j++)
            #pragma unroll
            for (int q = 0; q < 4; q++) acc[i][j][q] = 0.0f;

    float4 fa  = *(const float4*)(Ag);
    float4 fb0 = *(const float4*)(Bg);
    float4 fb1 = *(const float4*)(Bg + 64*KK);

    for (int k0 = 0; k0 < KK; k0 += 16) {
        As[rowA][cA+0] = f2tf(fa.x); As[rowA][cA+1] = f2tf(fa.y);
        As[rowA][cA+2] = f2tf(fa.z); As[rowA][cA+3] = f2tf(fa.w);
        Bs[rowB][cB+0] = f2tf(fb0.x); Bs[rowB][cB+1] = f2tf(fb0.y);
        Bs[rowB][cB+2] = f2tf(fb0.z); Bs[rowB][cB+3] = f2tf(fb0.w);
        Bs[rowB+64][cB+0] = f2tf(fb1.x); Bs[rowB+64][cB+1] = f2tf(fb1.y);
        Bs[rowB+64][cB+2] = f2tf(fb1.z); Bs[rowB+64][cB+3] = f2tf(fb1.w);
        __syncthreads();
        if (k0 + 16 < KK) {
            fa  = *(const float4*)(Ag + k0 + 16);
            fb0 = *(const float4*)(Bg + k0 + 16);
            fb1 = *(const float4*)(Bg + 64*KK + k0 + 16);
        }
        #pragma unroll
        for (int ks = 0; ks < 2; ks++) {
            unsigned a[2][4], b[4][2];
            #pragma unroll
            for (int mt = 0; mt < 2; mt++) {
                int m = warpM*32 + mt*16;
                a[mt][0] = As[m+g  ][ks*8+tg];
                a[mt][1] = As[m+g+8][ks*8+tg];
                a[mt][2] = As[m+g  ][ks*8+tg+4];
                a[mt][3] = As[m+g+8][ks*8+tg+4];
            }
            #pragma unroll
            for (int nt = 0; nt < 4; nt++) {
                int n = warpN*32 + nt*8;
                b[nt][0] = Bs[n+g][ks*8+tg];
                b[nt][1] = Bs[n+g][ks*8+tg+4];
            }
            #pragma unroll
            for (int mt = 0; mt < 2; mt++)
                #pragma unroll
                for (int nt = 0; nt < 4; nt++)
                    mma_tf32(acc[mt][nt], a[mt], b[nt]);
        }
        __syncthreads();
    }
    #pragma unroll
    for (int mt = 0; mt < 2; mt++) {
        #pragma unroll
        for (int nt = 0; nt < 4; nt++) {
            int m = m0 + warpM*32 + mt*16 + g;
            int n = n0 + warpN*32 + nt*8 + 2*tg;
            #pragma unroll
            for (int q = 0; q < 4; q++) {
                int mm = m + (q >> 1) * 8;
                int nn = n + (q & 1);
                float v = acc[mt][nt][q] + g_bias[nn];
                if (nn >= 1024 && nn < 1536) v += g_attI[(mm/Tq)*Hq + (nn - 1024)];
                g_pre[mm*NJ + nn] = v;
            }
        }
    }
}

// ---------------- tf32 rec GEMM with fused gather; split-K=4 ----------------
// BM=32 BN=128 BK=16; grid (20, nodes, 4)
__global__ __launch_bounds__(256, 2) void k_gemm_rec_tc(int base, const int* __restrict__ father)
{
    __shared__ unsigned As[32][20];
    __shared__ unsigned Bs[128][20];
    const int tid = threadIdx.x;
    const int wid = tid >> 5, lane = tid & 31;
    const int g = lane >> 2, tg = lane & 3;
    const int warpN = wid;
    const int m0 = blockIdx.y * 32, n0 = blockIdx.x * 128, z = blockIdx.z;

    // A loader meta: thread loads float2 at (rowA, kA)
    const int rowA = tid >> 3, kA = (tid & 7) * 2;
    const int rg = m0 + rowA;
    const int nn = rg >> 5, b = rg & 31;
    const int i = c_nodes[base + nn];
    const int f = father[b*Tq + i];
    const bool pa = (i > 0);
    const bool sb = (i > 0) && (((i - 1) % 3) != 0);
    const float* arow;
    if (z < 2) arow = pa ? (g_h + (b*Tq + f)*Hq + z*256 + kA) : (const float*)0;
    else       arow = sb ? (g_h + (b*Tq + i - 1)*Hq + (z-2)*256 + kA) : (const float*)0;

    const int rowB = tid >> 2, cB = (tid & 3) << 2;
    const float* Bg = g_Wrec + (n0 + rowB)*KK + z*256 + cB;

    float acc[2][2][4];
    #pragma unroll
    for (int mt = 0; mt < 2; mt++)
        #pragma unroll
        for (int nt = 0; nt < 2; nt++)
            #pragma unroll
            for (int q = 0; q < 4; q++) acc[mt][nt][q] = 0.0f;

    float2 fa = arow ? *(const float2*)(arow) : make_float2(0.f, 0.f);
    float4 fb0 = *(const float4*)(Bg);
    float4 fb1 = *(const float4*)(Bg + 64*KK);

    for (int k0 = 0; k0 < 256; k0 += 16) {
        As[rowA][kA+0] = f2tf(fa.x); As[rowA][kA+1] = f2tf(fa.y);
        Bs[rowB][cB+0] = f2tf(fb0.x); Bs[rowB][cB+1] = f2tf(fb0.y);
        Bs[rowB][cB+2] = f2tf(fb0.z); Bs[rowB][cB+3] = f2tf(fb0.w);
        Bs[rowB+64][cB+0] = f2tf(fb1.x); Bs[rowB+64][cB+1] = f2tf(fb1.y);
        Bs[rowB+64][cB+2] = f2tf(fb1.z); Bs[rowB+64][cB+3] = f2tf(fb1.w);
        __syncthreads();
        if (k0 + 16 < 256) {
            fa  = arow ? *(const float2*)(arow + k0 + 16) : make_float2(0.f, 0.f);
            fb0 = *(const float4*)(Bg + k0 + 16);
            fb1 = *(const float4*)(Bg + 64*KK + k0 + 16);
        }
        #pragma unroll
        for (int ks = 0; ks < 2; ks++) {
            unsigned a[2][4], bfr[2][2];
            #pragma unroll
            for (int mt = 0; mt < 2; mt++) {
                int m = mt*16;
                a[mt][0] = As[m+g  ][ks*8+tg];
                a[mt][1] = As[m+g+8][ks*8+tg];
                a[mt][2] = As[m+g  ][ks*8+tg+4];
                a[mt][3] = As[m+g+8][ks*8+tg+4];
            }
            #pragma unroll
            for (int nt = 0; nt < 2; nt++) {
                int n = warpN*16 + nt*8;
                bfr[nt][0] = Bs[n+g][ks*8+tg];
                bfr[nt][1] = Bs[n+g][ks*8+tg+4];
            }
            #pragma unroll
            for (int mt = 0; mt < 2; mt++)
                #pragma unroll
                for (int nt = 0; nt < 2; nt++)
                    mma_tf32(acc[mt][nt], a[mt], bfr[nt]);
        }
        __syncthreads();
    }
    #pragma unroll
    for (int mt = 0; mt < 2; mt++) {
        #pragma unroll
        for (int nt = 0; nt < 2; nt++) {
            int m = m0 + mt*16 + g;
            int n = n0 + warpN*16 + nt*8 + 2*tg;
            #pragma unroll
            for (int q = 0; q < 4; q++) {
                int mm = m + (q >> 1) * 8;
                int nnj = n + (q & 1);
                g_Rp[(z*MAXROWS + mm)*NJ + nnj] = acc[mt][nt][q];
            }
        }
    }
}

// ---------------- epilogue: combine, nonlinearities, h/c update ----------------
__global__ __launch_bounds__(256) void k_epi(int base, const int* __restrict__ father)
{
    int row = blockIdx.x;
    int u = blockIdx.y * 256 + threadIdx.x;
    int nn = row >> 5, b = row & 31;
    int i = c_nodes[base + nn];
    int f = father[b*Tq + i];
    int pr = (b*Tq + i)*NJ;
    float Rv[5];
    #pragma unroll
    for (int q = 0; q < 5; q++) {
        int j = q*512 + u;
        float v = g_pre[pr + j];
        v += g_Rp[(0*MAXROWS + row)*NJ + j];
        v += g_Rp[(1*MAXROWS + row)*NJ + j];
        v += g_Rp[(2*MAXROWS + row)*NJ + j];
        v += g_Rp[(3*MAXROWS + row)*NJ + j];
        Rv[q] = v;
    }
    float ig = sigf(Rv[0]);
    float og = sigf(Rv[1]);
    float cg = tanhf(Rv[2]);
    float f1 = sigf(Rv[3]);
    float f2 = sigf(Rv[4]);
    bool pa = (i > 0);
    bool sb = (i > 0) && (((i - 1) % 3) != 0);
    float hac = pa ? g_c[(b*Tq + f)*Hq + u]     : 0.0f;
    float hfc = sb ? g_c[(b*Tq + i - 1)*Hq + u] : 0.0f;
    float c = f1*hac + f2*hfc + ig*cg;
    float h = og * tanhf(c);
    g_h[(b*Tq + i)*Hq + u] = h;
    g_c[(b*Tq + i)*Hq + u] = c;
}

// ---------------- tf32 logits GEMM: out = h[3072,512] @ logit_W^T + logit_b ----------------
__global__ __launch_bounds__(256, 2) void k_gemm_logits_tc(
    const float* __restrict__ logit_W, const float* __restrict__ logit_b,
    float* __restrict__ out)
{
    __shared__ unsigned As[64][20];
    __shared__ unsigned Bs[128][20];
    const int tid = threadIdx.x;
    const int wid = tid >> 5, lane = tid & 31;
    const int g = lane >> 2, tg = lane & 3;
    const int warpM = wid & 1, warpN = wid >> 1;
    const int m0 = blockIdx.y * 64, n0 = blockIdx.x * 128;
    const int rowA = tid >> 2, cA = (tid & 3) << 2;
    const int rowB = tid >> 2, cB = cA;
    const float* Ag = g_h + (m0 + rowA)*Hq + cA;
    const bool bok0 = (n0 + rowB) < Vq;
    const bool bok1 = (n0 + rowB + 64) < Vq;
    const float* Bg = logit_W + (n0 + rowB)*Hq + cB;

    float acc[2][4][4];
    #pragma unroll
    for (int i2 = 0; i2 < 2; i2++)
        #pragma unroll
        for (int j = 0; j < 4; j++)
            #pragma unroll
            for (int q = 0; q < 4; q++) acc[i2][j][q] = 0.0f;

    float4 z4 = make_float4(0.f, 0.f, 0.f, 0.f);
    float4 fa  = *(const float4*)(Ag);
    float4 fb0 = bok0 ? *(const float4*)(Bg) : z4;
    float4 fb1 = bok1 ? *(const float4*)(Bg + 64*Hq) : z4;

    for (int k0 = 0; k0 < Hq; k0 += 16) {
        As[rowA][cA+0] = f2tf(fa.x); As[rowA][cA+1] = f2tf(fa.y);
        As[rowA][cA+2] = f2tf(fa.z); As[rowA][cA+3] = f2tf(fa.w);
        Bs[rowB][cB+0] = f2tf(fb0.x); Bs[rowB][cB+1] = f2tf(fb0.y);
        Bs[rowB][cB+2] = f2tf(fb0.z); Bs[rowB][cB+3] = f2tf(fb0.w);
        Bs[rowB+64][cB+0] = f2tf(fb1.x); Bs[rowB+64][cB+1] = f2tf(fb1.y);
        Bs[rowB+64][cB+2] = f2tf(fb1.z); Bs[rowB+64][cB+3] = f2tf(fb1.w);
        __syncthreads();
        if (k0 + 16 < Hq) {
            fa  = *(const float4*)(Ag + k0 + 16);
            fb0 = bok0 ? *(const float4*)(Bg + k0 + 16) : z4;
            fb1 = bok1 ? *(const float4*)(Bg + 64*Hq + k0 + 16) : z4;
        }
        #pragma unroll
        for (int ks = 0; ks < 2; ks++) {
            unsigned a[2][4], b[4][2];
            #pragma unroll
            for (int mt = 0; mt < 2; mt++) {
                int m = warpM*32 + mt*16;
                a[mt][0] = As[m+g  ][ks*8+tg];
                a[mt][1] = As[m+g+8][ks*8+tg];
                a[mt][2] = As[m+g  ][ks*8+tg+4];
                a[mt][3] = As[m+g+8][ks*8+tg+4];
            }
            #pragma unroll
            for (int nt = 0; nt < 4; nt++) {
                int n = warpN*32 + nt*8;
                b[nt][0] = Bs[n+g][ks*8+tg];
                b[nt][1] = Bs[n+g][ks*8+tg+4];
            }
            #pragma unroll
            for (int mt = 0; mt < 2; mt++)
                #pragma unroll
                for (int nt = 0; nt < 4; nt++)
                    mma_tf32(acc[mt][nt], a[mt], b[nt]);
        }
        __syncthreads();
    }
    #pragma unroll
    for (int mt = 0; mt < 2; mt++) {
        #pragma unroll
        for (int nt = 0; nt < 4; nt++) {
            int m = m0 + warpM*32 + mt*16 + g;
            int n = n0 + warpN*32 + nt*8 + 2*tg;
            #pragma unroll
            for (int q = 0; q < 4; q++) {
                int mm = m + (q >> 1) * 8;
                int nnv = n + (q & 1);
                if (nnv < Vq)
                    out[(long)mm*Vq + nnv] = acc[mt][nt][q] + logit_b[nnv];
            }
        }
    }
}

// ---------------- log_softmax ----------------
__global__ __launch_bounds__(256) void k_softmax(float* __restrict__ out)
{
    extern __shared__ float sx[];
    __shared__ float red[256];
    int r = blockIdx.x;
    int tid = threadIdx.x;
    float* px = out + (long)r * Vq;
    float m = -1e30f;
    for (int v = tid; v < Vq; v += 256) {
        float x = px[v];
        sx[v] = x;
        m = fmaxf(m, x);
    }
    red[tid] = m; __syncthreads();
    for (int s = 128; s > 0; s >>= 1) {
        if (tid < s) red[tid] = fmaxf(red[tid], red[tid + s]);
        __syncthreads();
    }
    float mx = red[0];
    __syncthreads();
    float s = 0.0f;
    for (int v = tid; v < Vq; v += 256) s += expf(sx[v] - mx);
    red[tid] = s; __syncthreads();
    for (int st = 128; st > 0; st >>= 1) {
        if (tid < st) red[tid] += red[tid + st];
        __syncthreads();
    }
    float ls = logf(red[0]);
    for (int v = tid; v < Vq; v += 256) px[v] = sx[v] - mx - ls;
}

// ---------------- launch ----------------
extern "C" void kernel_launch(void* const* d_in, const int* in_sizes, int n_in,
                              void* d_out, int out_size)
{
    const int*   word     = (const int*)  d_in[0];
    const int*   father   = (const int*)  d_in[1];
    const float* fc_feats = (const float*)d_in[2];
    const float* embed    = (const float*)d_in[3];
    const float* fc_W     = (const float*)d_in[4];
    const float* fc_b     = (const float*)d_in[5];
    const float* W_f1     = (const float*)d_in[6];
    const float* b_f1     = (const float*)d_in[7];
    const float* W_f2     = (const float*)d_in[8];
    const float* b_f2     = (const float*)d_in[9];
    const float* W_H      = (const float*)d_in[10];
    const float* b_H      = (const float*)d_in[11];
    const float* W_I      = (const float*)d_in[12];
    const float* b_I      = (const float*)d_in[13];
    const float* logit_W  = (const float*)d_in[14];
    const float* logit_b  = (const float*)d_in[15];
    float* out = (float*)d_out;

    k_setup<<<NJ, 256>>>(W_H, W_I, W_f1, W_f2, b_H, b_I, b_f1, b_f2);
    k_att <<<dim3(Eq/8, Bq), 256>>>(fc_feats, fc_W, fc_b);
    k_attI<<<dim3(Hq/8, Bq), 256>>>(W_I);
    k_xpre<<<MR, 256>>>(word, father, embed);
    k_gemm_pre_tc<<<dim3(NJ/128, MR/64), 256>>>();

    static const int sbase[13] = {0,1,2,3,4,7,10,13,22,31,40,59,78};
    static const int scnt [13] = {1,1,1,1,3,3,3,9,9,9,19,19,18};
    for (int s = 0; s < 13; s++) {
        int n = scnt[s];
        k_gemm_rec_tc<<<dim3(NJ/128, n, 4), 256>>>(sbase[s], father);
        k_epi<<<dim3(n*32, 2), 256>>>(sbase[s], father);
    }

    k_gemm_logits_tc<<<dim3((Vq + 127)/128, MR/64), 256>>>(logit_W, logit_b, out);
    k_softmax<<<MR, 256, Vq * sizeof(float)>>>(out);
}